// round 9
// baseline (speedup 1.0000x reference)
#include <cuda_runtime.h>
#include <cuda_bf16.h>
#include <mma.h>
#include <cstdint>

using namespace nvcuda;

#define NN 100000
#define NE 1600000
#define DD 128
#define KK 256   // concat K: [mean | h]

// ---------------- static device scratch (~167MB, within proven envelope) --------
__device__ float g_mean[(size_t)NN * DD];   // f32 mean aggregate
__device__ float g_buf0[(size_t)NN * DD];   // layer-1 output
__device__ float g_buf1[(size_t)NN * DD];   // layer-2 output
__device__ __nv_bfloat16 g_Whi[3 * KK * DD];  // concat weights hi
__device__ __nv_bfloat16 g_Wlo[3 * KK * DD];  // concat weights lo
// CSR (g_cnt statically zero-initialized; scan_kernel re-zeros it each launch)
__device__ int g_cnt[NN];
__device__ int g_rowptr[NN + 1];
__device__ int g_cursor[NN];
__device__ int g_csrc[NE];

// ---------------- CSR build ----------------
__global__ void hist_kernel(const int* __restrict__ dst) {
    int stride = gridDim.x * blockDim.x;
    for (int e = blockIdx.x * blockDim.x + threadIdx.x; e < NE; e += stride)
        atomicAdd(&g_cnt[dst[e]], 1);
}

// single block, 1024 threads: exclusive scan of g_cnt -> g_rowptr, copy to
// cursor, and RESET g_cnt to zero for the next launch (self-restoring state).
__global__ void scan_kernel() {
    __shared__ int sh[1024];
    const int t = threadIdx.x;
    const int chunk = (NN + 1023) / 1024;   // 98
    int start = t * chunk;
    int end   = min(start + chunk, NN);
    int s = 0;
    for (int j = start; j < end; j++) {
        g_rowptr[j] = s;
        s += g_cnt[j];
        g_cnt[j] = 0;        // restore for next launch
    }
    sh[t] = s;
    __syncthreads();
    for (int off = 1; off < 1024; off <<= 1) {
        int v = (t >= off) ? sh[t - off] : 0;
        __syncthreads();
        sh[t] += v;
        __syncthreads();
    }
    int excl = (t == 0) ? 0 : sh[t - 1];
    for (int j = start; j < end; j++) {
        int v = g_rowptr[j] + excl;
        g_rowptr[j] = v;
        g_cursor[j] = v;
    }
    if (t == 0) g_rowptr[NN] = NE;
}

__global__ void fill_kernel(const int* __restrict__ src, const int* __restrict__ dst) {
    int stride = gridDim.x * blockDim.x;
    for (int e = blockIdx.x * blockDim.x + threadIdx.x; e < NE; e += stride) {
        int p = atomicAdd(&g_cursor[dst[e]], 1);
        g_csrc[p] = src[e];
    }
}

// ---------------- weight conversion (hi/lo bf16 split, once per launch) --------
__global__ void convert_w_kernel(const float* __restrict__ Wl,
                                 const float* __restrict__ Wr) {
    int idx = blockIdx.x * blockDim.x + threadIdx.x;
    if (idx >= 3 * KK * DD) return;
    int l = idx / (KK * DD);
    int r = idx - l * (KK * DD);
    int k = r / DD;
    int n = r - k * DD;
    float v = (k < DD) ? Wl[(size_t)l * DD * DD + k * DD + n]
                       : Wr[(size_t)l * DD * DD + (k - DD) * DD + n];
    __nv_bfloat16 hi = __float2bfloat16_rn(v);
    g_Whi[idx] = hi;
    g_Wlo[idx] = __float2bfloat16_rn(v - __bfloat162float(hi));
}

// split a float4 into packed bf16x2 hi / lo words
__device__ __forceinline__ void split4(const float4 v, uint2* ph, uint2* pl) {
    __nv_bfloat162 h01, h23, l01, l23;
    h01.x = __float2bfloat16_rn(v.x); h01.y = __float2bfloat16_rn(v.y);
    h23.x = __float2bfloat16_rn(v.z); h23.y = __float2bfloat16_rn(v.w);
    l01.x = __float2bfloat16_rn(v.x - __bfloat162float(h01.x));
    l01.y = __float2bfloat16_rn(v.y - __bfloat162float(h01.y));
    l23.x = __float2bfloat16_rn(v.z - __bfloat162float(h23.x));
    l23.y = __float2bfloat16_rn(v.w - __bfloat162float(h23.y));
    uint2 h, l;
    h.x = *reinterpret_cast<unsigned*>(&h01); h.y = *reinterpret_cast<unsigned*>(&h23);
    l.x = *reinterpret_cast<unsigned*>(&l01); l.y = *reinterpret_cast<unsigned*>(&l23);
    *ph = h; *pl = l;
}

// ---------------- gather: one warp per node (CSR), MLP-4 unrolled --------------
__global__ void gather_kernel(const float* __restrict__ xin, int hsel) {
    const float* __restrict__ x =
        (hsel == 0) ? xin : (hsel == 1) ? (const float*)g_buf0 : (const float*)g_buf1;
    int n = (blockIdx.x * blockDim.x + threadIdx.x) >> 5;
    if (n >= NN) return;
    int lane = threadIdx.x & 31;
    int beg = g_rowptr[n];
    int end = g_rowptr[n + 1];
    float4 a0 = make_float4(0.f, 0.f, 0.f, 0.f);
    float4 a1 = make_float4(0.f, 0.f, 0.f, 0.f);
    float4 a2 = make_float4(0.f, 0.f, 0.f, 0.f);
    float4 a3 = make_float4(0.f, 0.f, 0.f, 0.f);
    int e = beg;
    for (; e + 4 <= end; e += 4) {
        int s0 = __ldg(&g_csrc[e + 0]);
        int s1 = __ldg(&g_csrc[e + 1]);
        int s2 = __ldg(&g_csrc[e + 2]);
        int s3 = __ldg(&g_csrc[e + 3]);
        float4 v0 = *reinterpret_cast<const float4*>(x + (size_t)s0 * DD + lane * 4);
        float4 v1 = *reinterpret_cast<const float4*>(x + (size_t)s1 * DD + lane * 4);
        float4 v2 = *reinterpret_cast<const float4*>(x + (size_t)s2 * DD + lane * 4);
        float4 v3 = *reinterpret_cast<const float4*>(x + (size_t)s3 * DD + lane * 4);
        a0.x += v0.x; a0.y += v0.y; a0.z += v0.z; a0.w += v0.w;
        a1.x += v1.x; a1.y += v1.y; a1.z += v1.z; a1.w += v1.w;
        a2.x += v2.x; a2.y += v2.y; a2.z += v2.z; a2.w += v2.w;
        a3.x += v3.x; a3.y += v3.y; a3.z += v3.z; a3.w += v3.w;
    }
    for (; e < end; e++) {
        int s = __ldg(&g_csrc[e]);
        float4 v = *reinterpret_cast<const float4*>(x + (size_t)s * DD + lane * 4);
        a0.x += v.x; a0.y += v.y; a0.z += v.z; a0.w += v.w;
    }
    float4 a;
    a.x = (a0.x + a1.x) + (a2.x + a3.x);
    a.y = (a0.y + a1.y) + (a2.y + a3.y);
    a.z = (a0.z + a1.z) + (a2.z + a3.z);
    a.w = (a0.w + a1.w) + (a2.w + a3.w);
    float invd = 1.f / fmaxf((float)(end - beg), 1.f);
    a.x *= invd; a.y *= invd; a.z *= invd; a.w *= invd;
    *reinterpret_cast<float4*>(g_mean + (size_t)n * DD + lane * 4) = a;
}

// ---------------- tensor-core GEMM (bf16 3-MMA split, reg-prefetch pipeline) ---
// Block 128x128, K=256, BK=32. 8 warps as 2(m)x4(n); warp tile 64x32.
#define ALD 40
#define BLD 136
#define SM_AHI 0
#define SM_ALO (128 * ALD * 2)                 // 10240
#define SM_BHI (SM_ALO + 128 * ALD * 2)        // 20480
#define SM_BLO (SM_BHI + 32 * BLD * 2)         // 29184
#define SM_TOT (SM_BLO + 32 * BLD * 2)         // 37888
#define STG_LD 132

__global__ __launch_bounds__(256, 2)
void sage_wmma_kernel(const float* __restrict__ xin,
                      float* __restrict__ oout,
                      const float* __restrict__ bias,
                      int lw, int hsel, int osel, int do_relu) {
    const float* __restrict__ h =
        (hsel == 0) ? xin : (hsel == 1) ? (const float*)g_buf0 : (const float*)g_buf1;
    float* __restrict__ out =
        (osel == 0) ? (float*)g_buf0 : (osel == 1) ? (float*)g_buf1 : oout;

    __shared__ __align__(16) char smem[SM_TOT];
    __nv_bfloat16* Ahi = reinterpret_cast<__nv_bfloat16*>(smem + SM_AHI);
    __nv_bfloat16* Alo = reinterpret_cast<__nv_bfloat16*>(smem + SM_ALO);
    __nv_bfloat16* Bhi = reinterpret_cast<__nv_bfloat16*>(smem + SM_BHI);
    __nv_bfloat16* Blo = reinterpret_cast<__nv_bfloat16*>(smem + SM_BLO);
    float* stage = reinterpret_cast<float*>(smem);   // [64][132] aliased

    const int tid = threadIdx.x;
    const int w  = tid >> 5;
    const int wm = w >> 2;              // 0..1 : 64-row group
    const int wn = w & 3;               // 0..3 : 32-col group
    const int rowBase = blockIdx.x * 128;

    // A-load: 2 threads per row; each handles 16 consecutive k (4 float4)
    const int ar = tid >> 1;            // 0..127
    const int akc = (tid & 1) * 16;     // 0 or 16
    const int agrow = rowBase + ar;
    const bool aval = agrow < NN;
    // B-load: 16 threads per k-row, 8 bf16 each
    const int kr = tid >> 4;            // 0..15
    const int nc = (tid & 15) * 8;      // 0..120

    wmma::fragment<wmma::accumulator, 16, 16, 16, float> acc[4][2];
    #pragma unroll
    for (int i = 0; i < 4; i++)
        #pragma unroll
        for (int j = 0; j < 2; j++) wmma::fill_fragment(acc[i][j], 0.f);

    // ---- register staging for the prefetch pipeline ----
    float4 ra[4];
    uint4  rbh[2], rbl[2];

    auto load_stage = [&](int kb) {
        const float* A = (kb < 4) ? g_mean : h;
        int k0 = (kb & 3) * 32 + akc;
        #pragma unroll
        for (int q = 0; q < 4; q++) {
            ra[q] = make_float4(0.f, 0.f, 0.f, 0.f);
            if (aval)
                ra[q] = *reinterpret_cast<const float4*>(A + (size_t)agrow * DD + k0 + q * 4);
        }
        #pragma unroll
        for (int half = 0; half < 2; half++) {
            int krow = kr + half * 16;
            size_t go = (size_t)lw + (size_t)(kb * 32 + krow) * DD + nc;
            rbh[half] = *reinterpret_cast<const uint4*>(g_Whi + go);
            rbl[half] = *reinterpret_cast<const uint4*>(g_Wlo + go);
        }
    };

    auto store_stage = [&]() {
        #pragma unroll
        for (int q = 0; q < 4; q++)
            split4(ra[q],
                   reinterpret_cast<uint2*>(Ahi + ar * ALD + akc + q * 4),
                   reinterpret_cast<uint2*>(Alo + ar * ALD + akc + q * 4));
        #pragma unroll
        for (int half = 0; half < 2; half++) {
            int krow = kr + half * 16;
            *reinterpret_cast<uint4*>(Bhi + krow * BLD + nc) = rbh[half];
            *reinterpret_cast<uint4*>(Blo + krow * BLD + nc) = rbl[half];
        }
    };

    load_stage(0);
    for (int kb = 0; kb < 8; kb++) {
        store_stage();
        __syncthreads();
        if (kb < 7) load_stage(kb + 1);   // global loads overlap the MMAs below

        #pragma unroll
        for (int kk = 0; kk < 32; kk += 16) {
            wmma::fragment<wmma::matrix_b, 16, 16, 16, __nv_bfloat16, wmma::row_major> bh[2], blo[2];
            #pragma unroll
            for (int j = 0; j < 2; j++) {
                wmma::load_matrix_sync(bh[j],  Bhi + kk * BLD + wn * 32 + j * 16, BLD);
                wmma::load_matrix_sync(blo[j], Blo + kk * BLD + wn * 32 + j * 16, BLD);
            }
            #pragma unroll
            for (int i = 0; i < 4; i++) {
                wmma::fragment<wmma::matrix_a, 16, 16, 16, __nv_bfloat16, wmma::row_major> ah, al;
                wmma::load_matrix_sync(ah, Ahi + (wm * 64 + i * 16) * ALD + kk, ALD);
                wmma::load_matrix_sync(al, Alo + (wm * 64 + i * 16) * ALD + kk, ALD);
                #pragma unroll
                for (int j = 0; j < 2; j++) {
                    wmma::mma_sync(acc[i][j], ah, bh[j],  acc[i][j]);
                    wmma::mma_sync(acc[i][j], ah, blo[j], acc[i][j]);
                    wmma::mma_sync(acc[i][j], al, bh[j],  acc[i][j]);
                }
            }
        }
        __syncthreads();
    }

    // ---- epilogue in two 64-row halves (stage aliases the tile smem) ----
    #pragma unroll
    for (int ph = 0; ph < 2; ph++) {
        if (wm == ph) {
            #pragma unroll
            for (int i = 0; i < 4; i++)
                #pragma unroll
                for (int j = 0; j < 2; j++)
                    wmma::store_matrix_sync(stage + (i * 16) * STG_LD + wn * 32 + j * 16,
                                            acc[i][j], STG_LD, wmma::mem_row_major);
        }
        __syncthreads();
        #pragma unroll
        for (int it = 0; it < 8; it++) {
            int idx = it * 256 + tid;          // 0..2047
            int row = idx >> 5;                // 0..63
            int c4  = (idx & 31) * 4;          // 0..124
            int grow = rowBase + ph * 64 + row;
            if (grow < NN) {
                const float* sp = stage + row * STG_LD + c4;
                float4 bb = *reinterpret_cast<const float4*>(bias + c4);
                float4 hv = *reinterpret_cast<const float4*>(h + (size_t)grow * DD + c4);
                float4 o;
                o.x = sp[0] + bb.x + hv.x;
                o.y = sp[1] + bb.y + hv.y;
                o.z = sp[2] + bb.z + hv.z;
                o.w = sp[3] + bb.w + hv.w;
                if (do_relu) {
                    o.x = fmaxf(o.x, 0.f); o.y = fmaxf(o.y, 0.f);
                    o.z = fmaxf(o.z, 0.f); o.w = fmaxf(o.w, 0.f);
                }
                *reinterpret_cast<float4*>(out + (size_t)grow * DD + c4) = o;
            }
        }
        __syncthreads();
    }
}

// ---------------- launch ----------------
extern "C" void kernel_launch(void* const* d_in, const int* in_sizes, int n_in,
                              void* d_out, int out_size) {
    const float* x  = (const float*)d_in[0];
    const int*   ei = (const int*)d_in[1];
    const float* Wl = (const float*)d_in[2];
    const float* bl = (const float*)d_in[3];
    const float* Wr = (const float*)d_in[4];
    const int* src = ei;
    const int* dst = ei + NE;
    float* out = (float*)d_out;

    const int SB = 1184;
    const int GATHERB = (NN * 32 + 255) / 256;   // one warp per node
    const int GB = (NN + 127) / 128;             // 782 gemm blocks

    // CSR build: g_cnt is zero on entry (static init / scan's reset last launch)
    hist_kernel<<<SB, 256>>>(dst);               // launch 1
    scan_kernel<<<1, 1024>>>();                  // launch 2 (also re-zeros g_cnt)
    fill_kernel<<<SB, 256>>>(src, dst);          // launch 3

    // layer 0 gather = launch 4 (ncu capture lands here)
    gather_kernel<<<GATHERB, 256>>>(x, 0);
    convert_w_kernel<<<(3 * KK * DD + 255) / 256, 256>>>(Wl, Wr);
    sage_wmma_kernel<<<GB, 256>>>(x, out, bl, 0 * KK * DD, 0, 0, 1);

    // layer 1
    gather_kernel<<<GATHERB, 256>>>(x, 1);
    sage_wmma_kernel<<<GB, 256>>>(x, out, bl + DD, 1 * KK * DD, 1, 1, 1);

    // layer 2
    gather_kernel<<<GATHERB, 256>>>(x, 2);
    sage_wmma_kernel<<<GB, 256>>>(x, out, bl + 2 * DD, 2 * KK * DD, 2, 2, 0);
}

// round 10
// speedup vs baseline: 1.0502x; 1.0502x over previous
#include <cuda_runtime.h>
#include <cuda_bf16.h>
#include <mma.h>
#include <cstdint>

using namespace nvcuda;

#define NN 100000
#define NE 1600000
#define DD 128
#define KK 256   // concat K: [mean | h]

// ---------------- static device scratch (~167MB, within proven envelope) --------
__device__ float g_mean[(size_t)NN * DD];   // f32 mean aggregate
__device__ float g_buf0[(size_t)NN * DD];   // layer-1 output
__device__ float g_buf1[(size_t)NN * DD];   // layer-2 output
__device__ __nv_bfloat16 g_Whi[3 * KK * DD];  // concat weights hi
__device__ __nv_bfloat16 g_Wlo[3 * KK * DD];  // concat weights lo
// CSR (g_cnt statically zero-initialized; scan_kernel re-zeros it each launch)
__device__ int g_cnt[NN];
__device__ int g_rowptr[NN + 1];
__device__ int g_cursor[NN];
__device__ int g_csrc[NE];

// ---------------- CSR build ----------------
__global__ void hist_kernel(const int* __restrict__ dst) {
    int stride = gridDim.x * blockDim.x;
    for (int e = blockIdx.x * blockDim.x + threadIdx.x; e < NE; e += stride)
        atomicAdd(&g_cnt[dst[e]], 1);
}

// single block, 1024 threads: exclusive scan of g_cnt -> g_rowptr, copy to
// cursor, and RESET g_cnt to zero for the next launch (self-restoring state).
__global__ void scan_kernel() {
    __shared__ int sh[1024];
    const int t = threadIdx.x;
    const int chunk = (NN + 1023) / 1024;   // 98
    int start = t * chunk;
    int end   = min(start + chunk, NN);
    int s = 0;
    for (int j = start; j < end; j++) {
        g_rowptr[j] = s;
        s += g_cnt[j];
        g_cnt[j] = 0;        // restore for next launch
    }
    sh[t] = s;
    __syncthreads();
    for (int off = 1; off < 1024; off <<= 1) {
        int v = (t >= off) ? sh[t - off] : 0;
        __syncthreads();
        sh[t] += v;
        __syncthreads();
    }
    int excl = (t == 0) ? 0 : sh[t - 1];
    for (int j = start; j < end; j++) {
        int v = g_rowptr[j] + excl;
        g_rowptr[j] = v;
        g_cursor[j] = v;
    }
    if (t == 0) g_rowptr[NN] = NE;
}

__global__ void fill_kernel(const int* __restrict__ src, const int* __restrict__ dst) {
    int stride = gridDim.x * blockDim.x;
    for (int e = blockIdx.x * blockDim.x + threadIdx.x; e < NE; e += stride) {
        int p = atomicAdd(&g_cursor[dst[e]], 1);
        g_csrc[p] = src[e];
    }
}

// ---------------- weight conversion (hi/lo bf16 split, once per launch) --------
__global__ void convert_w_kernel(const float* __restrict__ Wl,
                                 const float* __restrict__ Wr) {
    int idx = blockIdx.x * blockDim.x + threadIdx.x;
    if (idx >= 3 * KK * DD) return;
    int l = idx / (KK * DD);
    int r = idx - l * (KK * DD);
    int k = r / DD;
    int n = r - k * DD;
    float v = (k < DD) ? Wl[(size_t)l * DD * DD + k * DD + n]
                       : Wr[(size_t)l * DD * DD + (k - DD) * DD + n];
    __nv_bfloat16 hi = __float2bfloat16_rn(v);
    g_Whi[idx] = hi;
    g_Wlo[idx] = __float2bfloat16_rn(v - __bfloat162float(hi));
}

// split a float4 into packed bf16x2 hi / lo words
__device__ __forceinline__ void split4(const float4 v, uint2* ph, uint2* pl) {
    __nv_bfloat162 h01, h23, l01, l23;
    h01.x = __float2bfloat16_rn(v.x); h01.y = __float2bfloat16_rn(v.y);
    h23.x = __float2bfloat16_rn(v.z); h23.y = __float2bfloat16_rn(v.w);
    l01.x = __float2bfloat16_rn(v.x - __bfloat162float(h01.x));
    l01.y = __float2bfloat16_rn(v.y - __bfloat162float(h01.y));
    l23.x = __float2bfloat16_rn(v.z - __bfloat162float(h23.x));
    l23.y = __float2bfloat16_rn(v.w - __bfloat162float(h23.y));
    uint2 h, l;
    h.x = *reinterpret_cast<unsigned*>(&h01); h.y = *reinterpret_cast<unsigned*>(&h23);
    l.x = *reinterpret_cast<unsigned*>(&l01); l.y = *reinterpret_cast<unsigned*>(&l23);
    *ph = h; *pl = l;
}

// ---------------- gather: one warp per node (CSR), MLP-4 unrolled --------------
__global__ void gather_kernel(const float* __restrict__ xin, int hsel) {
    const float* __restrict__ x =
        (hsel == 0) ? xin : (hsel == 1) ? (const float*)g_buf0 : (const float*)g_buf1;
    int n = (blockIdx.x * blockDim.x + threadIdx.x) >> 5;
    if (n >= NN) return;
    int lane = threadIdx.x & 31;
    int beg = g_rowptr[n];
    int end = g_rowptr[n + 1];
    float4 a0 = make_float4(0.f, 0.f, 0.f, 0.f);
    float4 a1 = make_float4(0.f, 0.f, 0.f, 0.f);
    float4 a2 = make_float4(0.f, 0.f, 0.f, 0.f);
    float4 a3 = make_float4(0.f, 0.f, 0.f, 0.f);
    int e = beg;
    for (; e + 4 <= end; e += 4) {
        int s0 = __ldg(&g_csrc[e + 0]);
        int s1 = __ldg(&g_csrc[e + 1]);
        int s2 = __ldg(&g_csrc[e + 2]);
        int s3 = __ldg(&g_csrc[e + 3]);
        float4 v0 = *reinterpret_cast<const float4*>(x + (size_t)s0 * DD + lane * 4);
        float4 v1 = *reinterpret_cast<const float4*>(x + (size_t)s1 * DD + lane * 4);
        float4 v2 = *reinterpret_cast<const float4*>(x + (size_t)s2 * DD + lane * 4);
        float4 v3 = *reinterpret_cast<const float4*>(x + (size_t)s3 * DD + lane * 4);
        a0.x += v0.x; a0.y += v0.y; a0.z += v0.z; a0.w += v0.w;
        a1.x += v1.x; a1.y += v1.y; a1.z += v1.z; a1.w += v1.w;
        a2.x += v2.x; a2.y += v2.y; a2.z += v2.z; a2.w += v2.w;
        a3.x += v3.x; a3.y += v3.y; a3.z += v3.z; a3.w += v3.w;
    }
    for (; e < end; e++) {
        int s = __ldg(&g_csrc[e]);
        float4 v = *reinterpret_cast<const float4*>(x + (size_t)s * DD + lane * 4);
        a0.x += v.x; a0.y += v.y; a0.z += v.z; a0.w += v.w;
    }
    float4 a;
    a.x = (a0.x + a1.x) + (a2.x + a3.x);
    a.y = (a0.y + a1.y) + (a2.y + a3.y);
    a.z = (a0.z + a1.z) + (a2.z + a3.z);
    a.w = (a0.w + a1.w) + (a2.w + a3.w);
    float invd = 1.f / fmaxf((float)(end - beg), 1.f);
    a.x *= invd; a.y *= invd; a.z *= invd; a.w *= invd;
    *reinterpret_cast<float4*>(g_mean + (size_t)n * DD + lane * 4) = a;
}

// ---------------- tensor-core GEMM (bf16 3-MMA split, R8 structure) ------------
// Block 128x128, K=256, BK=32. 8 warps as 2(m)x4(n); warp tile 64x32.
#define ALD 40
#define BLD 136
#define SM_AHI 0
#define SM_ALO (128 * ALD * 2)                 // 10240
#define SM_BHI (SM_ALO + 128 * ALD * 2)        // 20480
#define SM_BLO (SM_BHI + 32 * BLD * 2)         // 29184
#define SM_TOT (SM_BLO + 32 * BLD * 2)         // 37888
#define STG_LD 132

__global__ __launch_bounds__(256, 2)
void sage_wmma_kernel(const float* __restrict__ xin,
                      float* __restrict__ oout,
                      const float* __restrict__ bias,
                      int lw, int hsel, int osel, int do_relu) {
    const float* __restrict__ h =
        (hsel == 0) ? xin : (hsel == 1) ? (const float*)g_buf0 : (const float*)g_buf1;
    float* __restrict__ out =
        (osel == 0) ? (float*)g_buf0 : (osel == 1) ? (float*)g_buf1 : oout;

    __shared__ __align__(16) char smem[SM_TOT];
    __nv_bfloat16* Ahi = reinterpret_cast<__nv_bfloat16*>(smem + SM_AHI);
    __nv_bfloat16* Alo = reinterpret_cast<__nv_bfloat16*>(smem + SM_ALO);
    __nv_bfloat16* Bhi = reinterpret_cast<__nv_bfloat16*>(smem + SM_BHI);
    __nv_bfloat16* Blo = reinterpret_cast<__nv_bfloat16*>(smem + SM_BLO);
    float* stage = reinterpret_cast<float*>(smem);   // [64][132] aliased

    const int tid = threadIdx.x;
    const int w  = tid >> 5;
    const int wm = w >> 2;              // 0..1 : 64-row group
    const int wn = w & 3;               // 0..3 : 32-col group
    const int rowBase = blockIdx.x * 128;

    // A-load: 2 threads per row; each handles 16 consecutive k (4 float4)
    const int ar = tid >> 1;            // 0..127
    const int akc = (tid & 1) * 16;     // 0 or 16
    const int agrow = rowBase + ar;
    const bool aval = agrow < NN;
    // B-load: 16 threads per k-row, 8 bf16 each
    const int kr = tid >> 4;            // 0..15
    const int nc = (tid & 15) * 8;      // 0..120

    wmma::fragment<wmma::accumulator, 16, 16, 16, float> acc[4][2];
    #pragma unroll
    for (int i = 0; i < 4; i++)
        #pragma unroll
        for (int j = 0; j < 2; j++) wmma::fill_fragment(acc[i][j], 0.f);

    for (int kb = 0; kb < 8; kb++) {
        // ---- A tile: 128 rows x 32 k, f32 load + split to bf16 hi/lo ----
        const float* A = (kb < 4) ? g_mean : h;
        int k0 = (kb & 3) * 32 + akc;
        #pragma unroll
        for (int q = 0; q < 4; q++) {
            float4 v = make_float4(0.f, 0.f, 0.f, 0.f);
            if (aval)
                v = *reinterpret_cast<const float4*>(A + (size_t)agrow * DD + k0 + q * 4);
            split4(v,
                   reinterpret_cast<uint2*>(Ahi + ar * ALD + akc + q * 4),
                   reinterpret_cast<uint2*>(Alo + ar * ALD + akc + q * 4));
        }
        // ---- B tile: 32 k x 128 n (pre-split bf16) ----
        #pragma unroll
        for (int half = 0; half < 2; half++) {
            int krow = kr + half * 16;
            size_t go = (size_t)lw + (size_t)(kb * 32 + krow) * DD + nc;
            *reinterpret_cast<uint4*>(Bhi + krow * BLD + nc) =
                *reinterpret_cast<const uint4*>(g_Whi + go);
            *reinterpret_cast<uint4*>(Blo + krow * BLD + nc) =
                *reinterpret_cast<const uint4*>(g_Wlo + go);
        }
        __syncthreads();

        #pragma unroll
        for (int kk = 0; kk < 32; kk += 16) {
            wmma::fragment<wmma::matrix_b, 16, 16, 16, __nv_bfloat16, wmma::row_major> bh[2], blo[2];
            #pragma unroll
            for (int j = 0; j < 2; j++) {
                wmma::load_matrix_sync(bh[j],  Bhi + kk * BLD + wn * 32 + j * 16, BLD);
                wmma::load_matrix_sync(blo[j], Blo + kk * BLD + wn * 32 + j * 16, BLD);
            }
            #pragma unroll
            for (int i = 0; i < 4; i++) {
                wmma::fragment<wmma::matrix_a, 16, 16, 16, __nv_bfloat16, wmma::row_major> ah, al;
                wmma::load_matrix_sync(ah, Ahi + (wm * 64 + i * 16) * ALD + kk, ALD);
                wmma::load_matrix_sync(al, Alo + (wm * 64 + i * 16) * ALD + kk, ALD);
                #pragma unroll
                for (int j = 0; j < 2; j++) {
                    wmma::mma_sync(acc[i][j], ah, bh[j],  acc[i][j]);
                    wmma::mma_sync(acc[i][j], ah, blo[j], acc[i][j]);
                    wmma::mma_sync(acc[i][j], al, bh[j],  acc[i][j]);
                }
            }
        }
        __syncthreads();
    }

    // ---- epilogue in two 64-row halves (stage aliases the tile smem) ----
    #pragma unroll
    for (int ph = 0; ph < 2; ph++) {
        if (wm == ph) {
            #pragma unroll
            for (int i = 0; i < 4; i++)
                #pragma unroll
                for (int j = 0; j < 2; j++)
                    wmma::store_matrix_sync(stage + (i * 16) * STG_LD + wn * 32 + j * 16,
                                            acc[i][j], STG_LD, wmma::mem_row_major);
        }
        __syncthreads();
        #pragma unroll
        for (int it = 0; it < 8; it++) {
            int idx = it * 256 + tid;          // 0..2047
            int row = idx >> 5;                // 0..63
            int c4  = (idx & 31) * 4;          // 0..124
            int grow = rowBase + ph * 64 + row;
            if (grow < NN) {
                const float* sp = stage + row * STG_LD + c4;
                float4 bb = *reinterpret_cast<const float4*>(bias + c4);
                float4 hv = *reinterpret_cast<const float4*>(h + (size_t)grow * DD + c4);
                float4 o;
                o.x = sp[0] + bb.x + hv.x;
                o.y = sp[1] + bb.y + hv.y;
                o.z = sp[2] + bb.z + hv.z;
                o.w = sp[3] + bb.w + hv.w;
                if (do_relu) {
                    o.x = fmaxf(o.x, 0.f); o.y = fmaxf(o.y, 0.f);
                    o.z = fmaxf(o.z, 0.f); o.w = fmaxf(o.w, 0.f);
                }
                *reinterpret_cast<float4*>(out + (size_t)grow * DD + c4) = o;
            }
        }
        __syncthreads();
    }
}

// ---------------- launch ----------------
extern "C" void kernel_launch(void* const* d_in, const int* in_sizes, int n_in,
                              void* d_out, int out_size) {
    const float* x  = (const float*)d_in[0];
    const int*   ei = (const int*)d_in[1];
    const float* Wl = (const float*)d_in[2];
    const float* bl = (const float*)d_in[3];
    const float* Wr = (const float*)d_in[4];
    const int* src = ei;
    const int* dst = ei + NE;
    float* out = (float*)d_out;

    const int SB = 1184;
    const int GATHERB = (NN * 32 + 255) / 256;   // one warp per node
    const int GB = (NN + 127) / 128;             // 782 gemm blocks

    // CSR build: g_cnt is zero on entry (static init / scan's reset last launch)
    hist_kernel<<<SB, 256>>>(dst);               // launch 1
    scan_kernel<<<1, 1024>>>();                  // launch 2 (also re-zeros g_cnt)
    fill_kernel<<<SB, 256>>>(src, dst);          // launch 3

    // layer 0
    gather_kernel<<<GATHERB, 256>>>(x, 0);       // launch 4
    convert_w_kernel<<<(3 * KK * DD + 255) / 256, 256>>>(Wl, Wr);
    sage_wmma_kernel<<<GB, 256>>>(x, out, bl, 0 * KK * DD, 0, 0, 1);  // launch 6

    // layer 1
    gather_kernel<<<GATHERB, 256>>>(x, 1);
    sage_wmma_kernel<<<GB, 256>>>(x, out, bl + DD, 1 * KK * DD, 1, 1, 1);

    // layer 2
    gather_kernel<<<GATHERB, 256>>>(x, 2);
    sage_wmma_kernel<<<GB, 256>>>(x, out, bl + 2 * DD, 2 * KK * DD, 2, 2, 0);
}